// round 1
// baseline (speedup 1.0000x reference)
#include <cuda_runtime.h>
#include <cstdint>
#include <math.h>

// Problem dims
#define B_   64
#define T_   512
#define NU_  256
#define NX_  1024

// Recurrence kernel config
#define GBLKS   128          // persistent blocks (<= 148 SMs, all co-resident)
#define CPB     8            // output columns per block (128*8 = 1024)
#define RTHREADS 256
#define KC      64           // k-chunk staged through smem
#define XS_LD   65           // padded row stride for x/g chunk (avoid bank conflicts)

// Phase-1 GEMM config
#define BM 64
#define BN 64
#define BK 16

// ---------------- device scratch (static: no allocations allowed) ----------------
__device__ float d_az[(size_t)B_ * T_ * NX_];
__device__ float d_af[(size_t)B_ * T_ * NX_];
__device__ float d_ar[(size_t)B_ * T_ * NX_];
__device__ float d_xA[B_ * NX_];
__device__ float d_xB[B_ * NX_];
__device__ float d_g[B_ * NX_];
__device__ unsigned d_barcount = 0;
__device__ unsigned d_bargen = 0;

// ---------------- grid-wide sense barrier (all blocks co-resident) ----------------
__device__ __forceinline__ void grid_barrier() {
    __syncthreads();
    if (threadIdx.x == 0) {
        __threadfence();                                  // release my global writes
        unsigned my_gen = *((volatile unsigned*)&d_bargen);
        unsigned arrived = atomicAdd(&d_barcount, 1u);
        if (arrived == GBLKS - 1) {
            atomicExch(&d_barcount, 0u);
            __threadfence();
            atomicAdd(&d_bargen, 1u);
        } else {
            while (*((volatile unsigned*)&d_bargen) == my_gen) {
                __nanosleep(32);
            }
        }
        __threadfence();                                  // acquire
    }
    __syncthreads();
}

// ---------------- Phase 1: a{z,f,r} = u @ W + b ----------------
// M = B*T = 32768, K = NU = 256, N = NX = 1024. gate = blockIdx.z.
__global__ void __launch_bounds__(256) inproj_kernel(
    const float* __restrict__ u,
    const float* __restrict__ Wz, const float* __restrict__ Wf, const float* __restrict__ Wr,
    const float* __restrict__ bz, const float* __restrict__ bf, const float* __restrict__ br)
{
    __shared__ float As[BM][BK + 1];   // +1 pad: avoid bank conflicts on column reads
    __shared__ float Bs[BK][BN];

    const int gate = blockIdx.z;
    const float* W    = (gate == 0) ? Wz : (gate == 1) ? Wf : Wr;
    const float* bias = (gate == 0) ? bz : (gate == 1) ? bf : br;
    float* out        = (gate == 0) ? d_az : (gate == 1) ? d_af : d_ar;

    const int m0 = blockIdx.y * BM;
    const int n0 = blockIdx.x * BN;
    const int tid = threadIdx.x;
    const int tx = tid % 16;           // 16 col groups of 4
    const int ty = tid / 16;           // 16 row groups of 4

    float acc[4][4];
#pragma unroll
    for (int i = 0; i < 4; i++)
#pragma unroll
        for (int j = 0; j < 4; j++) acc[i][j] = 0.0f;

    for (int k0 = 0; k0 < NU_; k0 += BK) {
        // load A tile: 64x16 (256 float4)
        {
            const int r = tid >> 2;            // 0..63
            const int q = tid & 3;             // 0..3
            float4 v = *(const float4*)&u[(size_t)(m0 + r) * NU_ + k0 + q * 4];
            As[r][q * 4 + 0] = v.x; As[r][q * 4 + 1] = v.y;
            As[r][q * 4 + 2] = v.z; As[r][q * 4 + 3] = v.w;
        }
        // load B tile: 16x64 (256 float4)
        {
            const int r = tid >> 4;            // 0..15
            const int q = tid & 15;            // 0..15
            float4 v = *(const float4*)&W[(size_t)(k0 + r) * NX_ + n0 + q * 4];
            *(float4*)&Bs[r][q * 4] = v;
        }
        __syncthreads();
#pragma unroll
        for (int kk = 0; kk < BK; ++kk) {
            float a[4];
#pragma unroll
            for (int i = 0; i < 4; i++) a[i] = As[ty * 4 + i][kk];
            float4 bv = *(float4*)&Bs[kk][tx * 4];
            float b[4] = {bv.x, bv.y, bv.z, bv.w};
#pragma unroll
            for (int i = 0; i < 4; i++)
#pragma unroll
                for (int j = 0; j < 4; j++) acc[i][j] += a[i] * b[j];
        }
        __syncthreads();
    }

#pragma unroll
    for (int j = 0; j < 4; j++) {
        const float bj = __ldg(&bias[n0 + tx * 4 + j]);
#pragma unroll
        for (int i = 0; i < 4; i++) {
            out[(size_t)(m0 + ty * 4 + i) * NX_ + n0 + tx * 4 + j] = acc[i][j] + bj;
        }
    }
}

// ---------------- Phase 2: persistent recurrence ----------------
// Block bid owns output columns [bid*8, bid*8+8) for all gates, all 64 batch rows.
// Thread (c = tid&7, g = tid>>3) computes rows b0=g, b1=g+32 of its column.
extern __shared__ float recur_smem[];

__global__ void __launch_bounds__(RTHREADS, 1) recur_kernel(
    const float* __restrict__ Uz, const float* __restrict__ Uf, const float* __restrict__ Ur,
    const float* __restrict__ x0, float* __restrict__ out)
{
    float* Uzs = recur_smem;                 // [NX_][CPB]
    float* Ufs = Uzs + NX_ * CPB;
    float* Urs = Ufs + NX_ * CPB;
    float* xs  = Urs + NX_ * CPB;            // [B_][XS_LD] chunk buffer (reused for g)

    const int tid = threadIdx.x;
    const int bid = blockIdx.x;
    const int j0 = bid * CPB;
    const int c  = tid & (CPB - 1);
    const int g  = tid >> 3;                 // 0..31
    const int b0 = g, b1 = g + 32;
    const int jc = j0 + c;

    // Stage this block's U column slices into smem (one-time)
    for (int i = tid; i < NX_ * CPB; i += RTHREADS) {
        const int k = i / CPB, cc = i & (CPB - 1);
        Uzs[i] = __ldg(&Uz[(size_t)k * NX_ + j0 + cc]);
        Ufs[i] = __ldg(&Uf[(size_t)k * NX_ + j0 + cc]);
        Urs[i] = __ldg(&Ur[(size_t)k * NX_ + j0 + cc]);
    }

    // Cooperative init of state buffer A from x0 (each block a disjoint span)
    {
        const int span = (B_ * NX_) / GBLKS;       // 512
        const int base = bid * span;
        for (int i = tid; i < span; i += RTHREADS)
            __stcg(&d_xA[base + i], x0[base + i]);
    }
    grid_barrier();

    float* xcur  = d_xA;
    float* xnext = d_xB;

    for (int t = 0; t < T_; ++t) {
        const size_t aoff0 = ((size_t)b0 * T_ + t) * NX_ + jc;
        const size_t aoff1 = ((size_t)b1 * T_ + t) * NX_ + jc;

        // ---- ZF phase: z = sig(az + x@Uz), f = sig(af + x@Uf) ----
        float accz0 = __ldcs(&d_az[aoff0]);
        float accz1 = __ldcs(&d_az[aoff1]);
        float accf0 = __ldcs(&d_af[aoff0]);
        float accf1 = __ldcs(&d_af[aoff1]);

        for (int kc = 0; kc < NX_ / KC; ++kc) {
            __syncthreads();   // previous chunk consumers done
            const int base = kc * KC;
            for (int l = tid; l < (B_ * KC) / 4; l += RTHREADS) {
                const int row = l / (KC / 4);
                const int q   = l % (KC / 4);
                float4 v = __ldcg((const float4*)&xcur[row * NX_ + base + q * 4]);
                float* dst = &xs[row * XS_LD + q * 4];
                dst[0] = v.x; dst[1] = v.y; dst[2] = v.z; dst[3] = v.w;
            }
            __syncthreads();
#pragma unroll
            for (int kk = 0; kk < KC; ++kk) {
                const float xv0 = xs[b0 * XS_LD + kk];
                const float xv1 = xs[b1 * XS_LD + kk];
                const float uz  = Uzs[(base + kk) * CPB + c];
                const float uf  = Ufs[(base + kk) * CPB + c];
                accz0 += xv0 * uz; accz1 += xv1 * uz;
                accf0 += xv0 * uf; accf1 += xv1 * uf;
            }
        }
        const float z0 = 1.0f / (1.0f + expf(-accz0));
        const float z1 = 1.0f / (1.0f + expf(-accz1));
        const float f0 = 1.0f / (1.0f + expf(-accf0));
        const float f1 = 1.0f / (1.0f + expf(-accf1));
        const float xc0 = __ldcg(&xcur[b0 * NX_ + jc]);
        const float xc1 = __ldcg(&xcur[b1 * NX_ + jc]);
        __stcg(&d_g[b0 * NX_ + jc], f0 * xc0);
        __stcg(&d_g[b1 * NX_ + jc], f1 * xc1);
        // io_delay: output at step t is the PRE-update state
        __stcs(&out[aoff0], xc0);
        __stcs(&out[aoff1], xc1);

        grid_barrier();   // all g written

        // ---- R phase: r = tanh(ar + (f*x)@Ur); x_next = z*x + (1-z)*r ----
        float accr0 = __ldcs(&d_ar[aoff0]);
        float accr1 = __ldcs(&d_ar[aoff1]);

        for (int kc = 0; kc < NX_ / KC; ++kc) {
            __syncthreads();
            const int base = kc * KC;
            for (int l = tid; l < (B_ * KC) / 4; l += RTHREADS) {
                const int row = l / (KC / 4);
                const int q   = l % (KC / 4);
                float4 v = __ldcg((const float4*)&d_g[row * NX_ + base + q * 4]);
                float* dst = &xs[row * XS_LD + q * 4];
                dst[0] = v.x; dst[1] = v.y; dst[2] = v.z; dst[3] = v.w;
            }
            __syncthreads();
#pragma unroll
            for (int kk = 0; kk < KC; ++kk) {
                const float gv0 = xs[b0 * XS_LD + kk];
                const float gv1 = xs[b1 * XS_LD + kk];
                const float ur  = Urs[(base + kk) * CPB + c];
                accr0 += gv0 * ur; accr1 += gv1 * ur;
            }
        }
        const float r0 = tanhf(accr0);
        const float r1 = tanhf(accr1);
        __stcg(&xnext[b0 * NX_ + jc], z0 * xc0 + (1.0f - z0) * r0);
        __stcg(&xnext[b1 * NX_ + jc], z1 * xc1 + (1.0f - z1) * r1);

        grid_barrier();   // x_next fully written before anyone reads it

        float* tmp = xcur; xcur = xnext; xnext = tmp;
    }
}

// ---------------- launch ----------------
extern "C" void kernel_launch(void* const* d_in, const int* in_sizes, int n_in,
                              void* d_out, int out_size) {
    const float* u  = (const float*)d_in[0];
    const float* x0 = (const float*)d_in[1];
    const float* Wz = (const float*)d_in[2];
    const float* Uz = (const float*)d_in[3];
    const float* bz = (const float*)d_in[4];
    const float* Wf = (const float*)d_in[5];
    const float* Uf = (const float*)d_in[6];
    const float* bf = (const float*)d_in[7];
    const float* Wr = (const float*)d_in[8];
    const float* Ur = (const float*)d_in[9];
    const float* br = (const float*)d_in[10];
    float* out = (float*)d_out;

    // Phase 1: input projections for all 3 gates
    dim3 g1(NX_ / BN, (B_ * T_) / BM, 3);
    inproj_kernel<<<g1, 256>>>(u, Wz, Wf, Wr, bz, bf, br);

    // Phase 2: persistent recurrence
    const int smem_bytes = (3 * NX_ * CPB + B_ * XS_LD) * (int)sizeof(float);  // ~114.9 KB
    cudaFuncSetAttribute(recur_kernel, cudaFuncAttributeMaxDynamicSharedMemorySize, smem_bytes);
    recur_kernel<<<GBLKS, RTHREADS, smem_bytes>>>(Uz, Uf, Ur, x0, out);
}

// round 2
// speedup vs baseline: 1.0720x; 1.0720x over previous
#include <cuda_runtime.h>
#include <cstdint>
#include <math.h>

// Problem dims
#define B_   64
#define T_   512
#define NU_  256
#define NX_  1024

// Recurrence kernel config
#define GBLKS    128         // persistent blocks (<= 148 SMs, all co-resident)
#define CPB      8           // output columns per block (128*8 = 1024)
#define RTHREADS 256
#define KC       128         // k-chunk staged through smem
#define NCH      (NX_ / KC)  // 8 chunks per phase
#define XLD      (KC + 4)    // padded row stride (132 floats): 16B-aligned, conflict-free
#define XBUF     (B_ * XLD)  // one chunk buffer in floats (8448)

// Phase-1 GEMM config
#define BM 64
#define BN 64
#define BK 16

// ---------------- device scratch (static: no allocations allowed) ----------------
__device__ float d_az[(size_t)B_ * T_ * NX_];
__device__ float d_af[(size_t)B_ * T_ * NX_];
__device__ float d_ar[(size_t)B_ * T_ * NX_];
__device__ float d_xA[B_ * NX_];
__device__ float d_xB[B_ * NX_];
__device__ float d_g[B_ * NX_];
__device__ unsigned d_barcount = 0;
__device__ unsigned d_bargen = 0;

// ---------------- cp.async helpers ----------------
__device__ __forceinline__ void cp_async16(void* smem_dst, const void* gmem_src) {
    uint32_t saddr = (uint32_t)__cvta_generic_to_shared(smem_dst);
    asm volatile("cp.async.cg.shared.global [%0], [%1], 16;\n" :: "r"(saddr), "l"(gmem_src));
}
__device__ __forceinline__ void cp_commit() {
    asm volatile("cp.async.commit_group;\n");
}
template <int N>
__device__ __forceinline__ void cp_wait() {
    asm volatile("cp.async.wait_group %0;\n" :: "n"(N));
}

// Load one 64 x KC chunk of `src` (row stride NX_) starting at column kb into smem buf.
// 2048 x 16B transfers; 8 per thread. L1-bypassing (.cg) for cross-SM coherence.
__device__ __forceinline__ void load_chunk(float* dst, const float* src, int kb, int tid) {
#pragma unroll
    for (int q = 0; q < 8; ++q) {
        const int idx = tid + q * RTHREADS;   // 0..2047
        const int row = idx >> 5;             // 32 float4 per row
        const int c4  = idx & 31;
        cp_async16(dst + row * XLD + c4 * 4, src + (size_t)row * NX_ + kb + c4 * 4);
    }
    cp_commit();
}

// ---------------- grid-wide sense barrier (all blocks co-resident) ----------------
__device__ __forceinline__ void grid_barrier() {
    __syncthreads();
    if (threadIdx.x == 0) {
        __threadfence();                                  // release my global writes
        unsigned my_gen = *((volatile unsigned*)&d_bargen);
        unsigned arrived = atomicAdd(&d_barcount, 1u);
        if (arrived == GBLKS - 1) {
            atomicExch(&d_barcount, 0u);
            __threadfence();
            atomicAdd(&d_bargen, 1u);
        } else {
            while (*((volatile unsigned*)&d_bargen) == my_gen) {
                __nanosleep(20);
            }
        }
        __threadfence();                                  // acquire
    }
    __syncthreads();
}

// ---------------- Phase 1: a{z,f,r} = u @ W + b ----------------
__global__ void __launch_bounds__(256) inproj_kernel(
    const float* __restrict__ u,
    const float* __restrict__ Wz, const float* __restrict__ Wf, const float* __restrict__ Wr,
    const float* __restrict__ bz, const float* __restrict__ bf, const float* __restrict__ br)
{
    __shared__ float As[BM][BK + 1];
    __shared__ float Bs[BK][BN];

    const int gate = blockIdx.z;
    const float* W    = (gate == 0) ? Wz : (gate == 1) ? Wf : Wr;
    const float* bias = (gate == 0) ? bz : (gate == 1) ? bf : br;
    float* out        = (gate == 0) ? d_az : (gate == 1) ? d_af : d_ar;

    const int m0 = blockIdx.y * BM;
    const int n0 = blockIdx.x * BN;
    const int tid = threadIdx.x;
    const int tx = tid % 16;
    const int ty = tid / 16;

    float acc[4][4];
#pragma unroll
    for (int i = 0; i < 4; i++)
#pragma unroll
        for (int j = 0; j < 4; j++) acc[i][j] = 0.0f;

    for (int k0 = 0; k0 < NU_; k0 += BK) {
        {
            const int r = tid >> 2;
            const int q = tid & 3;
            float4 v = *(const float4*)&u[(size_t)(m0 + r) * NU_ + k0 + q * 4];
            As[r][q * 4 + 0] = v.x; As[r][q * 4 + 1] = v.y;
            As[r][q * 4 + 2] = v.z; As[r][q * 4 + 3] = v.w;
        }
        {
            const int r = tid >> 4;
            const int q = tid & 15;
            float4 v = *(const float4*)&W[(size_t)(k0 + r) * NX_ + n0 + q * 4];
            *(float4*)&Bs[r][q * 4] = v;
        }
        __syncthreads();
#pragma unroll
        for (int kk = 0; kk < BK; ++kk) {
            float a[4];
#pragma unroll
            for (int i = 0; i < 4; i++) a[i] = As[ty * 4 + i][kk];
            float4 bv = *(float4*)&Bs[kk][tx * 4];
            float b[4] = {bv.x, bv.y, bv.z, bv.w};
#pragma unroll
            for (int i = 0; i < 4; i++)
#pragma unroll
                for (int j = 0; j < 4; j++) acc[i][j] += a[i] * b[j];
        }
        __syncthreads();
    }

#pragma unroll
    for (int j = 0; j < 4; j++) {
        const float bj = __ldg(&bias[n0 + tx * 4 + j]);
#pragma unroll
        for (int i = 0; i < 4; i++) {
            out[(size_t)(m0 + ty * 4 + i) * NX_ + n0 + tx * 4 + j] = acc[i][j] + bj;
        }
    }
}

// ---------------- Phase 2: persistent recurrence ----------------
// Block bid owns columns [bid*8, bid*8+8). Thread = (row r = tid>>2, colpair cg = tid&3):
// computes 1 row x 2 consecutive columns per gate. U loads are float2 from smem.
extern __shared__ float recur_smem[];

__global__ void __launch_bounds__(RTHREADS, 1) recur_kernel(
    const float* __restrict__ Uz, const float* __restrict__ Uf, const float* __restrict__ Ur,
    const float* __restrict__ x0, float* __restrict__ out)
{
    float* Uzs = recur_smem;                 // [NX_][8]
    float* Ufs = Uzs + NX_ * CPB;
    float* Urs = Ufs + NX_ * CPB;
    float* xs  = Urs + NX_ * CPB;            // [2][B_][XLD] double-buffered chunk

    const int tid = threadIdx.x;
    const int bid = blockIdx.x;
    const int j0 = bid * CPB;
    const int r  = tid >> 2;                 // 0..63  (batch row)
    const int cg = tid & 3;                  // 0..3   (column pair)
    const int jc = j0 + 2 * cg;

    const float2* Uz2 = (const float2*)Uzs;  // index k*4 + cg
    const float2* Uf2 = (const float2*)Ufs;
    const float2* Ur2 = (const float2*)Urs;

    // Stage this block's U column slices into smem (one-time)
    for (int i = tid; i < NX_ * CPB; i += RTHREADS) {
        const int k = i >> 3, cc = i & 7;
        Uzs[i] = __ldg(&Uz[(size_t)k * NX_ + j0 + cc]);
        Ufs[i] = __ldg(&Uf[(size_t)k * NX_ + j0 + cc]);
        Urs[i] = __ldg(&Ur[(size_t)k * NX_ + j0 + cc]);
    }

    // Cooperative init of state buffer A from x0
    {
        const int span = (B_ * NX_) / GBLKS;   // 512
        const int base = bid * span;
        for (int i = tid; i < span; i += RTHREADS)
            __stcg(&d_xA[base + i], x0[base + i]);
    }
    grid_barrier();

    float* xcur  = d_xA;
    float* xnext = d_xB;

    for (int t = 0; t < T_; ++t) {
        const size_t aoff = ((size_t)r * T_ + t) * NX_ + jc;

        // ================= ZF phase: z = sig(az + x@Uz), f = sig(af + x@Uf) =================
        float2 azv = __ldcs((const float2*)&d_az[aoff]);
        float2 afv = __ldcs((const float2*)&d_af[aoff]);
        float accza = azv.x, acczb = azv.y;
        float accfa = afv.x, accfb = afv.y;

        load_chunk(xs, xcur, 0, tid);          // prologue: chunk 0 -> buf 0
#pragma unroll 1
        for (int kc = 0; kc < NCH; ++kc) {
            if (kc + 1 < NCH) { load_chunk(xs + ((kc + 1) & 1) * XBUF, xcur, (kc + 1) * KC, tid); cp_wait<1>(); }
            else              { cp_wait<0>(); }
            __syncthreads();
            const float* xb = xs + (kc & 1) * XBUF + r * XLD;
            const int kb4 = kc * KC * 4;
#pragma unroll 8
            for (int kk = 0; kk < KC; ++kk) {
                const float xv = xb[kk];
                const float2 uz = Uz2[kb4 + kk * 4 + cg];
                const float2 uf = Uf2[kb4 + kk * 4 + cg];
                accza += xv * uz.x; acczb += xv * uz.y;
                accfa += xv * uf.x; accfb += xv * uf.y;
            }
            __syncthreads();
        }
        const float za = 1.0f / (1.0f + __expf(-accza));
        const float zb = 1.0f / (1.0f + __expf(-acczb));
        const float fa = 1.0f / (1.0f + __expf(-accfa));
        const float fb = 1.0f / (1.0f + __expf(-accfb));
        const float2 xc = __ldcg((const float2*)&xcur[(size_t)r * NX_ + jc]);
        {
            float2 gv; gv.x = fa * xc.x; gv.y = fb * xc.y;
            __stcg((float2*)&d_g[(size_t)r * NX_ + jc], gv);
        }
        // io_delay: output at step t is the PRE-update state
        __stcs((float2*)&out[aoff], xc);

        grid_barrier();   // all of g visible

        // ================= R phase: r = tanh(ar + g@Ur); x_next = z*x + (1-z)*r ============
        float2 arv = __ldcs((const float2*)&d_ar[aoff]);
        float accra = arv.x, accrb = arv.y;

        load_chunk(xs, d_g, 0, tid);
#pragma unroll 1
        for (int kc = 0; kc < NCH; ++kc) {
            if (kc + 1 < NCH) { load_chunk(xs + ((kc + 1) & 1) * XBUF, d_g, (kc + 1) * KC, tid); cp_wait<1>(); }
            else              { cp_wait<0>(); }
            __syncthreads();
            const float* gb = xs + (kc & 1) * XBUF + r * XLD;
            const int kb4 = kc * KC * 4;
#pragma unroll 8
            for (int kk = 0; kk < KC; ++kk) {
                const float gv = gb[kk];
                const float2 ur = Ur2[kb4 + kk * 4 + cg];
                accra += gv * ur.x; accrb += gv * ur.y;
            }
            __syncthreads();
        }
        const float ra = tanhf(accra);
        const float rb = tanhf(accrb);
        {
            float2 xn;
            xn.x = za * xc.x + (1.0f - za) * ra;
            xn.y = zb * xc.y + (1.0f - zb) * rb;
            __stcg((float2*)&xnext[(size_t)r * NX_ + jc], xn);
        }

        grid_barrier();   // x_next fully written before anyone reads it

        float* tmp = xcur; xcur = xnext; xnext = tmp;
    }
}

// ---------------- launch ----------------
extern "C" void kernel_launch(void* const* d_in, const int* in_sizes, int n_in,
                              void* d_out, int out_size) {
    const float* u  = (const float*)d_in[0];
    const float* x0 = (const float*)d_in[1];
    const float* Wz = (const float*)d_in[2];
    const float* Uz = (const float*)d_in[3];
    const float* bz = (const float*)d_in[4];
    const float* Wf = (const float*)d_in[5];
    const float* Uf = (const float*)d_in[6];
    const float* bf = (const float*)d_in[7];
    const float* Wr = (const float*)d_in[8];
    const float* Ur = (const float*)d_in[9];
    const float* br = (const float*)d_in[10];
    float* out = (float*)d_out;

    // Phase 1: input projections for all 3 gates
    dim3 g1(NX_ / BN, (B_ * T_) / BM, 3);
    inproj_kernel<<<g1, 256>>>(u, Wz, Wf, Wr, bz, bf, br);

    // Phase 2: persistent recurrence
    const int smem_bytes = (3 * NX_ * CPB + 2 * XBUF) * (int)sizeof(float);  // 165,888 B
    cudaFuncSetAttribute(recur_kernel, cudaFuncAttributeMaxDynamicSharedMemorySize, smem_bytes);
    recur_kernel<<<GBLKS, RTHREADS, smem_bytes>>>(Uz, Uf, Ur, x0, out);
}

// round 4
// speedup vs baseline: 2.0917x; 1.9512x over previous
#include <cuda_runtime.h>
#include <cstdint>
#include <math.h>

// Problem dims
#define B_   64
#define T_   512
#define NU_  256
#define NX_  1024

// Recurrence kernel config
#define GBLKS    128         // persistent blocks (<= 148 SMs, all co-resident)
#define CPB      8           // output columns per block (128*8 = 1024)
#define RTHREADS 256
#define KC       128         // k-chunk staged through smem
#define NCH      (NX_ / KC)  // 8 chunks per phase
#define XLD      (KC + 4)    // padded row stride (132 floats, 16B-aligned rows)
#define XBUF     (B_ * XLD)  // one chunk buffer in floats (8448)

// Phase-1 GEMM config
#define BM 64
#define BN 64
#define BK 16

// ---------------- device scratch (static: no allocations allowed) ----------------
__device__ float d_az[(size_t)B_ * T_ * NX_];
__device__ float d_af[(size_t)B_ * T_ * NX_];
__device__ float d_ar[(size_t)B_ * T_ * NX_];
__device__ float d_xA[B_ * NX_];
__device__ float d_xB[B_ * NX_];
__device__ float d_g[B_ * NX_];
__device__ unsigned d_barcount;

// ---------------- cp.async helpers ----------------
__device__ __forceinline__ void cp_async16(void* smem_dst, const void* gmem_src) {
    uint32_t saddr = (uint32_t)__cvta_generic_to_shared(smem_dst);
    asm volatile("cp.async.cg.shared.global [%0], [%1], 16;\n" :: "r"(saddr), "l"(gmem_src));
}
__device__ __forceinline__ void cp_commit() {
    asm volatile("cp.async.commit_group;\n");
}
template <int N>
__device__ __forceinline__ void cp_wait() {
    asm volatile("cp.async.wait_group %0;\n" :: "n"(N));
}

// Load one 64 x KC chunk of `src` (row stride NX_) starting at column kb into smem buf.
// 2048 x 16B transfers; 8 per thread. L2-direct (.cg) for cross-SM coherence.
__device__ __forceinline__ void load_chunk(float* dst, const float* src, int kb, int tid) {
#pragma unroll
    for (int q = 0; q < 8; ++q) {
        const int idx = tid + q * RTHREADS;   // 0..2047
        const int row = idx >> 5;             // 32 float4 per row
        const int c4  = idx & 31;
        cp_async16(dst + row * XLD + c4 * 4, src + (size_t)row * NX_ + kb + c4 * 4);
    }
    cp_commit();
}

// ---------------- grid-wide monotone barrier (all blocks co-resident) ----------------
// Counter is reset to 0 by init_kernel each launch; target advances by GBLKS per barrier.
__device__ __forceinline__ void grid_barrier(unsigned target) {
    __syncthreads();
    if (threadIdx.x == 0) {
        unsigned old;
        asm volatile("atom.add.release.gpu.global.u32 %0, [%1], 1;"
                     : "=r"(old) : "l"(&d_barcount) : "memory");
        unsigned cur;
        do {
            asm volatile("ld.acquire.gpu.global.u32 %0, [%1];"
                         : "=r"(cur) : "l"(&d_barcount) : "memory");
        } while (cur < target);
    }
    __syncthreads();
}

// ---------------- init: reset barrier counter + copy x0 into state buffer ----------------
__global__ void init_kernel(const float* __restrict__ x0) {
    if (blockIdx.x == 0 && threadIdx.x == 0) d_barcount = 0;
    const int i = blockIdx.x * blockDim.x + threadIdx.x;   // grid covers B_*NX_/4
    float4 v = *(const float4*)&x0[i * 4];
    *(float4*)&d_xA[i * 4] = v;
}

// ---------------- Phase 1: a{z,f,r} = u @ W + b ----------------
__global__ void __launch_bounds__(256) inproj_kernel(
    const float* __restrict__ u,
    const float* __restrict__ Wz, const float* __restrict__ Wf, const float* __restrict__ Wr,
    const float* __restrict__ bz, const float* __restrict__ bf, const float* __restrict__ br)
{
    __shared__ float As[BM][BK + 1];
    __shared__ float Bs[BK][BN];

    const int gate = blockIdx.z;
    const float* W    = (gate == 0) ? Wz : (gate == 1) ? Wf : Wr;
    const float* bias = (gate == 0) ? bz : (gate == 1) ? bf : br;
    float* out        = (gate == 0) ? d_az : (gate == 1) ? d_af : d_ar;

    const int m0 = blockIdx.y * BM;
    const int n0 = blockIdx.x * BN;
    const int tid = threadIdx.x;
    const int tx = tid % 16;
    const int ty = tid / 16;

    float acc[4][4];
#pragma unroll
    for (int i = 0; i < 4; i++)
#pragma unroll
        for (int j = 0; j < 4; j++) acc[i][j] = 0.0f;

    for (int k0 = 0; k0 < NU_; k0 += BK) {
        {
            const int r = tid >> 2;
            const int q = tid & 3;
            float4 v = *(const float4*)&u[(size_t)(m0 + r) * NU_ + k0 + q * 4];
            As[r][q * 4 + 0] = v.x; As[r][q * 4 + 1] = v.y;
            As[r][q * 4 + 2] = v.z; As[r][q * 4 + 3] = v.w;
        }
        {
            const int r = tid >> 4;
            const int q = tid & 15;
            float4 v = *(const float4*)&W[(size_t)(k0 + r) * NX_ + n0 + q * 4];
            *(float4*)&Bs[r][q * 4] = v;
        }
        __syncthreads();
#pragma unroll
        for (int kk = 0; kk < BK; ++kk) {
            float a[4];
#pragma unroll
            for (int i = 0; i < 4; i++) a[i] = As[ty * 4 + i][kk];
            float4 bv = *(float4*)&Bs[kk][tx * 4];
            float b[4] = {bv.x, bv.y, bv.z, bv.w};
#pragma unroll
            for (int i = 0; i < 4; i++)
#pragma unroll
                for (int j = 0; j < 4; j++) acc[i][j] += a[i] * b[j];
        }
        __syncthreads();
    }

#pragma unroll
    for (int j = 0; j < 4; j++) {
        const float bj = __ldg(&bias[n0 + tx * 4 + j]);
#pragma unroll
        for (int i = 0; i < 4; i++) {
            out[(size_t)(m0 + ty * 4 + i) * NX_ + n0 + tx * 4 + j] = acc[i][j] + bj;
        }
    }
}

// ---------------- Phase 2: persistent recurrence ----------------
// ZF phase: gate-split — threads 0..127 compute z (1 row x 4 cols), 128..255 compute f.
// R  phase: all 256 threads, 1 row x 2 cols.
extern __shared__ float recur_smem[];

__global__ void __launch_bounds__(RTHREADS, 1) recur_kernel(
    const float* __restrict__ Uz, const float* __restrict__ Uf, const float* __restrict__ Ur,
    float* __restrict__ out)
{
    float* Uzs  = recur_smem;                // [NX_][8]
    float* Ufs  = Uzs + NX_ * CPB;
    float* Urs  = Ufs + NX_ * CPB;
    float* xs   = Urs + NX_ * CPB;           // [2][B_][XLD] double-buffered chunk
    float* zbuf = xs + 2 * XBUF;             // [64][8] z values for R epilogue

    const int tid = threadIdx.x;
    const int bid = blockIdx.x;
    const int j0 = bid * CPB;

    // ZF mapping
    const int half = tid >> 7;               // 0 = z, 1 = f
    const int t7   = tid & 127;
    const int zr   = t7 >> 1;                // 0..63
    const int ui   = t7 & 1;                 // which float4 of the 8 cols
    const int zc   = ui * 4;                 // col offset within block
    // R mapping
    const int r2 = tid >> 2;                 // 0..63
    const int q2 = tid & 3;                  // 0..3
    const int c2 = q2 * 2;

    const float4* Ug4 = (const float4*)(half ? Ufs : Uzs);
    const float2* Ur2 = (const float2*)Urs;

    // Stage this block's U column slices into smem (one-time)
    for (int i = tid; i < NX_ * CPB; i += RTHREADS) {
        const int k = i >> 3, cc = i & 7;
        Uzs[i] = __ldg(&Uz[(size_t)k * NX_ + j0 + cc]);
        Ufs[i] = __ldg(&Uf[(size_t)k * NX_ + j0 + cc]);
        Urs[i] = __ldg(&Ur[(size_t)k * NX_ + j0 + cc]);
    }
    __syncthreads();

    float* xcur  = d_xA;
    float* xnext = d_xB;
    unsigned target = GBLKS;

    for (int t = 0; t < T_; ++t) {
        // ================= ZF phase: z = sig(az + x@Uz), f = sig(af + x@Uf) ============
        {
            const float* a_base = half ? d_af : d_az;
            const float4 av = __ldcs((const float4*)&a_base[((size_t)zr * T_ + t) * NX_ + j0 + zc]);
            float a0 = 0.f, a1 = 0.f, a2 = 0.f, a3 = 0.f;

            load_chunk(xs, xcur, 0, tid);
#pragma unroll 1
            for (int kc = 0; kc < NCH; ++kc) {
                if (kc + 1 < NCH) { load_chunk(xs + ((kc + 1) & 1) * XBUF, xcur, (kc + 1) * KC, tid); cp_wait<1>(); }
                else              { cp_wait<0>(); }
                __syncthreads();
                const float*  xb  = xs + (kc & 1) * XBUF + zr * XLD;
                const float4* u4p = Ug4 + (size_t)kc * KC * 2 + ui;
#pragma unroll 8
                for (int kk = 0; kk < KC; ++kk) {
                    const float  xv = xb[kk];
                    const float4 uv = u4p[(size_t)kk * 2];
                    a0 += xv * uv.x; a1 += xv * uv.y;
                    a2 += xv * uv.z; a3 += xv * uv.w;
                }
                __syncthreads();
            }
            a0 += av.x; a1 += av.y; a2 += av.z; a3 += av.w;
            const float s0 = 1.0f / (1.0f + __expf(-a0));
            const float s1 = 1.0f / (1.0f + __expf(-a1));
            const float s2 = 1.0f / (1.0f + __expf(-a2));
            const float s3 = 1.0f / (1.0f + __expf(-a3));

            const float4 xc = __ldcg((const float4*)&xcur[(size_t)zr * NX_ + j0 + zc]);
            if (half == 0) {
                zbuf[zr * 8 + zc + 0] = s0; zbuf[zr * 8 + zc + 1] = s1;
                zbuf[zr * 8 + zc + 2] = s2; zbuf[zr * 8 + zc + 3] = s3;
                // io_delay: output at step t is the PRE-update state
                __stcs((float4*)&out[((size_t)zr * T_ + t) * NX_ + j0 + zc], xc);
            } else {
                float4 g4;
                g4.x = s0 * xc.x; g4.y = s1 * xc.y; g4.z = s2 * xc.z; g4.w = s3 * xc.w;
                __stcg((float4*)&d_g[(size_t)zr * NX_ + j0 + zc], g4);
            }
        }
        grid_barrier(target); target += GBLKS;   // g fully visible; zbuf synced

        // ================= R phase: r = tanh(ar + g@Ur); x_next = z*x + (1-z)*r ========
        {
            const float2 arv = __ldcs((const float2*)&d_ar[((size_t)r2 * T_ + t) * NX_ + j0 + c2]);
            float ra = 0.f, rb = 0.f;

            load_chunk(xs, d_g, 0, tid);
#pragma unroll 1
            for (int kc = 0; kc < NCH; ++kc) {
                if (kc + 1 < NCH) { load_chunk(xs + ((kc + 1) & 1) * XBUF, d_g, (kc + 1) * KC, tid); cp_wait<1>(); }
                else              { cp_wait<0>(); }
                __syncthreads();
                const float*  gb = xs + (kc & 1) * XBUF + r2 * XLD;
                const float2* up = Ur2 + (size_t)kc * KC * 4 + q2;
#pragma unroll 8
                for (int kk = 0; kk < KC; ++kk) {
                    const float  gv = gb[kk];
                    const float2 uv = up[(size_t)kk * 4];
                    ra += gv * uv.x; rb += gv * uv.y;
                }
                __syncthreads();
            }
            ra += arv.x; rb += arv.y;
            const float rta = tanhf(ra);
            const float rtb = tanhf(rb);

            const float2 xc2 = __ldcg((const float2*)&xcur[(size_t)r2 * NX_ + j0 + c2]);
            const float za = zbuf[r2 * 8 + c2 + 0];
            const float zb = zbuf[r2 * 8 + c2 + 1];
            float2 xn;
            xn.x = za * xc2.x + (1.0f - za) * rta;
            xn.y = zb * xc2.y + (1.0f - zb) * rtb;
            __stcg((float2*)&xnext[(size_t)r2 * NX_ + j0 + c2], xn);
        }
        grid_barrier(target); target += GBLKS;   // x_next fully written

        float* tmp = xcur; xcur = xnext; xnext = tmp;
    }
}

// ---------------- launch ----------------
extern "C" void kernel_launch(void* const* d_in, const int* in_sizes, int n_in,
                              void* d_out, int out_size) {
    const float* u  = (const float*)d_in[0];
    const float* x0 = (const float*)d_in[1];
    const float* Wz = (const float*)d_in[2];
    const float* Uz = (const float*)d_in[3];
    const float* bz = (const float*)d_in[4];
    const float* Wf = (const float*)d_in[5];
    const float* Uf = (const float*)d_in[6];
    const float* bf = (const float*)d_in[7];
    const float* Wr = (const float*)d_in[8];
    const float* Ur = (const float*)d_in[9];
    const float* br = (const float*)d_in[10];
    float* out = (float*)d_out;

    // Init: reset barrier counter + x0 -> state buffer (B_*NX_/4 = 16384 float4)
    init_kernel<<<64, 256>>>(x0);

    // Phase 1: input projections for all 3 gates
    dim3 g1(NX_ / BN, (B_ * T_) / BM, 3);
    inproj_kernel<<<g1, 256>>>(u, Wz, Wf, Wr, bz, bf, br);

    // Phase 2: persistent recurrence
    const int smem_bytes = (3 * NX_ * CPB + 2 * XBUF + 512) * (int)sizeof(float);  // 167,936 B
    cudaFuncSetAttribute(recur_kernel, cudaFuncAttributeMaxDynamicSharedMemorySize, smem_bytes);
    recur_kernel<<<GBLKS, RTHREADS, smem_bytes>>>(Uz, Uf, Ur, out);
}

// round 6
// speedup vs baseline: 2.5537x; 1.2209x over previous
#include <cuda_runtime.h>
#include <cstdint>
#include <math.h>

// Problem dims
#define B_   64
#define T_   512
#define NU_  256
#define NX_  1024

// Recurrence kernel config
#define GBLKS    128         // persistent blocks (all co-resident)
#define CPB      8           // output columns per block
#define RTHREADS 256
#define KC       64          // k-chunk size
#define NCHK     16          // chunks per phase
#define NBUF     6           // chunk buffers (3 pairs in flight)
#define XLD      68          // padded row stride (272B: 16B-aligned)
#define BUFF     (B_ * XLD)  // one chunk buffer in floats (4352)

// Phase-1 GEMM config
#define BM 64
#define BN 64
#define BK 16

typedef unsigned long long u64;

// ---------------- device scratch ----------------
__device__ float d_az[(size_t)B_ * T_ * NX_];
__device__ float d_af[(size_t)B_ * T_ * NX_];
__device__ float d_ar[(size_t)B_ * T_ * NX_];
__device__ float d_xA[B_ * NX_];
__device__ float d_xB[B_ * NX_];
__device__ float d_g[B_ * NX_];
__device__ unsigned d_barcount;

// ---------------- packed f32x2 helpers (sm_103a) ----------------
__device__ __forceinline__ u64 pack2(float x, float y) {
    u64 r; asm("mov.b64 %0, {%1,%2};" : "=l"(r) : "f"(x), "f"(y)); return r;
}
__device__ __forceinline__ void ffma2(u64& d, u64 a, u64 b) {
    asm("fma.rn.f32x2 %0, %1, %2, %0;" : "+l"(d) : "l"(a), "l"(b));
}
__device__ __forceinline__ u64 fadd2(u64 a, u64 b) {
    u64 r; asm("add.rn.f32x2 %0, %1, %2;" : "=l"(r) : "l"(a), "l"(b)); return r;
}
__device__ __forceinline__ void unpack2(u64 v, float& x, float& y) {
    asm("mov.b64 {%0,%1}, %2;" : "=f"(x), "=f"(y) : "l"(v));
}

// ---------------- cp.async helpers ----------------
__device__ __forceinline__ void cp_async16(void* smem_dst, const void* gmem_src) {
    uint32_t saddr = (uint32_t)__cvta_generic_to_shared(smem_dst);
    asm volatile("cp.async.cg.shared.global [%0], [%1], 16;\n" :: "r"(saddr), "l"(gmem_src));
}
__device__ __forceinline__ void cp_commit() { asm volatile("cp.async.commit_group;\n"); }
template <int N>
__device__ __forceinline__ void cp_wait() { asm volatile("cp.async.wait_group %0;\n" :: "n"(N)); }

// Load chunk pair (2*pair, 2*pair+1) of src [64][NX_] into ring buffers. One commit group.
__device__ __forceinline__ void load_pair(float* bufs, const float* src, int pair, int tid) {
#pragma unroll
    for (int h = 0; h < 2; ++h) {
        const int c = 2 * pair + h;
        float* dst = bufs + (c % NBUF) * BUFF;
        const int cb = c * KC;
#pragma unroll
        for (int q = 0; q < 4; ++q) {
            const int idx = tid + q * RTHREADS;   // 0..1023
            const int row = idx >> 4;             // 16 float4 per row
            const int c4  = idx & 15;
            cp_async16(dst + row * XLD + c4 * 4, src + (size_t)row * NX_ + cb + c4 * 4);
        }
    }
    cp_commit();
}

// ---------------- grid-wide monotone barrier ----------------
// Counter reset by init_kernel each launch; target advances by GBLKS per barrier.
// Light nanosleep backoff keeps 128 pollers from hammering one L2 line.
__device__ __forceinline__ void grid_barrier(unsigned target) {
    __syncthreads();
    if (threadIdx.x == 0) {
        unsigned old;
        asm volatile("atom.add.release.gpu.global.u32 %0, [%1], 1;"
                     : "=r"(old) : "l"(&d_barcount) : "memory");
        unsigned cur;
        int spins = 0;
        do {
            asm volatile("ld.acquire.gpu.global.u32 %0, [%1];"
                         : "=r"(cur) : "l"(&d_barcount) : "memory");
            if (cur >= target) break;
            if (++spins > 4) __nanosleep(40);
        } while (true);
    }
    __syncthreads();
}

// ---------------- init ----------------
__global__ void init_kernel(const float* __restrict__ x0) {
    if (blockIdx.x == 0 && threadIdx.x == 0) d_barcount = 0;
    const int i = blockIdx.x * blockDim.x + threadIdx.x;
    float4 v = *(const float4*)&x0[i * 4];
    *(float4*)&d_xA[i * 4] = v;
}

// ---------------- Phase 1: a{z,f,r} = u @ W + b ----------------
__global__ void __launch_bounds__(256) inproj_kernel(
    const float* __restrict__ u,
    const float* __restrict__ Wz, const float* __restrict__ Wf, const float* __restrict__ Wr,
    const float* __restrict__ bz, const float* __restrict__ bf, const float* __restrict__ br)
{
    __shared__ float As[BM][BK + 1];
    __shared__ float Bs[BK][BN];

    const int gate = blockIdx.z;
    const float* W    = (gate == 0) ? Wz : (gate == 1) ? Wf : Wr;
    const float* bias = (gate == 0) ? bz : (gate == 1) ? bf : br;
    float* out        = (gate == 0) ? d_az : (gate == 1) ? d_af : d_ar;

    const int m0 = blockIdx.y * BM;
    const int n0 = blockIdx.x * BN;
    const int tid = threadIdx.x;
    const int tx = tid % 16;
    const int ty = tid / 16;

    float acc[4][4];
#pragma unroll
    for (int i = 0; i < 4; i++)
#pragma unroll
        for (int j = 0; j < 4; j++) acc[i][j] = 0.0f;

    for (int k0 = 0; k0 < NU_; k0 += BK) {
        {
            const int r = tid >> 2, q = tid & 3;
            float4 v = *(const float4*)&u[(size_t)(m0 + r) * NU_ + k0 + q * 4];
            As[r][q * 4 + 0] = v.x; As[r][q * 4 + 1] = v.y;
            As[r][q * 4 + 2] = v.z; As[r][q * 4 + 3] = v.w;
        }
        {
            const int r = tid >> 4, q = tid & 15;
            float4 v = *(const float4*)&W[(size_t)(k0 + r) * NX_ + n0 + q * 4];
            *(float4*)&Bs[r][q * 4] = v;
        }
        __syncthreads();
#pragma unroll
        for (int kk = 0; kk < BK; ++kk) {
            float a[4];
#pragma unroll
            for (int i = 0; i < 4; i++) a[i] = As[ty * 4 + i][kk];
            float4 bv = *(float4*)&Bs[kk][tx * 4];
            float b[4] = {bv.x, bv.y, bv.z, bv.w};
#pragma unroll
            for (int i = 0; i < 4; i++)
#pragma unroll
                for (int j = 0; j < 4; j++) acc[i][j] += a[i] * b[j];
        }
        __syncthreads();
    }

#pragma unroll
    for (int j = 0; j < 4; j++) {
        const float bj = __ldg(&bias[n0 + tx * 4 + j]);
#pragma unroll
        for (int i = 0; i < 4; i++)
            out[(size_t)(m0 + ty * 4 + i) * NX_ + n0 + tx * 4 + j] = acc[i][j] + bj;
    }
}

// ---------------- Phase 2: persistent recurrence ----------------
// 128 slots: slot s -> row = s>>1, ui = s&1 (4 cols: j0 + ui*4).
// khalf = tid>>7: 0 -> even chunks (warps 0-3), 1 -> odd chunks (warps 4-7).
// ZF dual-gate: acc_c = {z_c, f_c} via fma.rn.f32x2 with Uz/Uf interleaved.
extern __shared__ float recur_smem[];

__global__ void __launch_bounds__(RTHREADS, 1) recur_kernel(
    const float* __restrict__ Uz, const float* __restrict__ Uf, const float* __restrict__ Ur,
    float* __restrict__ out)
{
    float* Uzf  = recur_smem;                  // [NX_][8 cols][2 gates] = 16384 f
    float* Urs  = Uzf + NX_ * 16;              // [NX_][8] = 8192 f
    float* bufs = Urs + NX_ * 8;               // 6 * 4352 f
    u64*   scr  = (u64*)(bufs + NBUF * BUFF);  // 512 u64 reduction scratch

    const int tid = threadIdx.x;
    const int bid = blockIdx.x;
    const int j0 = bid * CPB;

    const int s     = tid & 127;
    const int khalf = tid >> 7;
    const int row   = s >> 1;
    const int ui    = s & 1;
    const int jb    = j0 + ui * 4;

    // Stage U slices (one-time). Uzf interleaved {Uz, Uf} per column.
    for (int i = tid; i < NX_ * 8; i += RTHREADS) {
        const int k = i >> 3, col = i & 7;
        Uzf[k * 16 + col * 2 + 0] = __ldg(&Uz[(size_t)k * NX_ + j0 + col]);
        Uzf[k * 16 + col * 2 + 1] = __ldg(&Uf[(size_t)k * NX_ + j0 + col]);
        Urs[i]                    = __ldg(&Ur[(size_t)k * NX_ + j0 + col]);
    }
    __syncthreads();

    const ulonglong2* UzfT = (const ulonglong2*)Uzf + ui * 2;   // + k*4 per k
    const ulonglong2* UrT  = (const ulonglong2*)Urs + ui;       // + k*2 per k

    float* xcur  = d_xA;
    float* xnext = d_xB;
    unsigned target = GBLKS;

    float zv[4];     // z gate values (khalf==0 threads)
    float4 xc;       // current state for this thread's 4 cols

    for (int t = 0; t < T_; ++t) {
        // ================= ZF phase =================
        u64 acc0 = 0, acc1 = 0, acc2 = 0, acc3 = 0;
        float4 az4, af4;
        if (khalf == 0) {
            az4 = __ldcs((const float4*)&d_az[((size_t)row * T_ + t) * NX_ + jb]);
            af4 = __ldcs((const float4*)&d_af[((size_t)row * T_ + t) * NX_ + jb]);
        }

        load_pair(bufs, xcur, 0, tid);
        load_pair(bufs, xcur, 1, tid);
        load_pair(bufs, xcur, 2, tid);
#pragma unroll 1
        for (int p = 0; p < 8; ++p) {
            if (p < 6) cp_wait<2>(); else if (p == 6) cp_wait<1>(); else cp_wait<0>();
            __syncthreads();
            const int c = 2 * p + khalf;
            const float* xb = bufs + (c % NBUF) * BUFF + row * XLD;
            const int k0 = c * KC;
#pragma unroll 4
            for (int kk2 = 0; kk2 < KC / 2; ++kk2) {
                const float2 xp = *(const float2*)(xb + kk2 * 2);
                const u64 p0 = pack2(xp.x, xp.x);
                const u64 p1 = pack2(xp.y, xp.y);
                const int k = k0 + kk2 * 2;
                ulonglong2 A0 = UzfT[(size_t)k * 4];
                ulonglong2 B0 = UzfT[(size_t)k * 4 + 1];
                ffma2(acc0, p0, A0.x); ffma2(acc1, p0, A0.y);
                ffma2(acc2, p0, B0.x); ffma2(acc3, p0, B0.y);
                ulonglong2 A1 = UzfT[(size_t)(k + 1) * 4];
                ulonglong2 B1 = UzfT[(size_t)(k + 1) * 4 + 1];
                ffma2(acc0, p1, A1.x); ffma2(acc1, p1, A1.y);
                ffma2(acc2, p1, B1.x); ffma2(acc3, p1, B1.y);
            }
            __syncthreads();
            if (p < 5) load_pair(bufs, xcur, p + 3, tid);
        }
        // cross-half reduction
        if (khalf == 1) {
            ((ulonglong2*)scr)[s * 2 + 0] = make_ulonglong2(acc0, acc1);
            ((ulonglong2*)scr)[s * 2 + 1] = make_ulonglong2(acc2, acc3);
        }
        __syncthreads();
        if (khalf == 0) {
            ulonglong2 o0 = ((ulonglong2*)scr)[s * 2 + 0];
            ulonglong2 o1 = ((ulonglong2*)scr)[s * 2 + 1];
            acc0 = fadd2(acc0, o0.x); acc1 = fadd2(acc1, o0.y);
            acc2 = fadd2(acc2, o1.x); acc3 = fadd2(acc3, o1.y);

            float zp[4], fp[4];
            unpack2(acc0, zp[0], fp[0]); unpack2(acc1, zp[1], fp[1]);
            unpack2(acc2, zp[2], fp[2]); unpack2(acc3, zp[3], fp[3]);
            zp[0] += az4.x; zp[1] += az4.y; zp[2] += az4.z; zp[3] += az4.w;
            fp[0] += af4.x; fp[1] += af4.y; fp[2] += af4.z; fp[3] += af4.w;
            float fv[4];
#pragma unroll
            for (int c2 = 0; c2 < 4; ++c2) {
                zv[c2] = 1.0f / (1.0f + __expf(-zp[c2]));
                fv[c2] = 1.0f / (1.0f + __expf(-fp[c2]));
            }
            xc = __ldcg((const float4*)&xcur[(size_t)row * NX_ + jb]);
            // io_delay: output at step t is the PRE-update state
            __stcs((float4*)&out[((size_t)row * T_ + t) * NX_ + jb], xc);
            float4 g4;
            g4.x = fv[0] * xc.x; g4.y = fv[1] * xc.y;
            g4.z = fv[2] * xc.z; g4.w = fv[3] * xc.w;
            __stcg((float4*)&d_g[(size_t)row * NX_ + jb], g4);
        }
        grid_barrier(target); target += GBLKS;

        // ================= R phase =================
        u64 racc0 = 0, racc1 = 0;
        float4 ar4;
        if (khalf == 0)
            ar4 = __ldcs((const float4*)&d_ar[((size_t)row * T_ + t) * NX_ + jb]);

        load_pair(bufs, d_g, 0, tid);
        load_pair(bufs, d_g, 1, tid);
        load_pair(bufs, d_g, 2, tid);
#pragma unroll 1
        for (int p = 0; p < 8; ++p) {
            if (p < 6) cp_wait<2>(); else if (p == 6) cp_wait<1>(); else cp_wait<0>();
            __syncthreads();
            const int c = 2 * p + khalf;
            const float* gb = bufs + (c % NBUF) * BUFF + row * XLD;
            const int k0 = c * KC;
#pragma unroll 4
            for (int kk2 = 0; kk2 < KC / 2; ++kk2) {
                const float2 gp = *(const float2*)(gb + kk2 * 2);
                const u64 p0 = pack2(gp.x, gp.x);
                const u64 p1 = pack2(gp.y, gp.y);
                const int k = k0 + kk2 * 2;
                ulonglong2 U0 = UrT[(size_t)k * 2];
                ffma2(racc0, p0, U0.x); ffma2(racc1, p0, U0.y);
                ulonglong2 U1 = UrT[(size_t)(k + 1) * 2];
                ffma2(racc0, p1, U1.x); ffma2(racc1, p1, U1.y);
            }
            __syncthreads();
            if (p < 5) load_pair(bufs, d_g, p + 3, tid);
        }
        if (khalf == 1)
            ((ulonglong2*)scr)[s] = make_ulonglong2(racc0, racc1);
        __syncthreads();
        if (khalf == 0) {
            ulonglong2 o = ((ulonglong2*)scr)[s];
            racc0 = fadd2(racc0, o.x); racc1 = fadd2(racc1, o.y);
            float rp[4];
            unpack2(racc0, rp[0], rp[1]); unpack2(racc1, rp[2], rp[3]);
            rp[0] += ar4.x; rp[1] += ar4.y; rp[2] += ar4.z; rp[3] += ar4.w;
            float4 xn;
            xn.x = zv[0] * xc.x + (1.0f - zv[0]) * tanhf(rp[0]);
            xn.y = zv[1] * xc.y + (1.0f - zv[1]) * tanhf(rp[1]);
            xn.z = zv[2] * xc.z + (1.0f - zv[2]) * tanhf(rp[2]);
            xn.w = zv[3] * xc.w + (1.0f - zv[3]) * tanhf(rp[3]);
            __stcg((float2*)&xnext[(size_t)row * NX_ + jb], make_float2(xn.x, xn.y));
            __stcg((float2*)&xnext[(size_t)row * NX_ + jb + 2], make_float2(xn.z, xn.w));
        }
        grid_barrier(target); target += GBLKS;

        float* tmp = xcur; xcur = xnext; xnext = tmp;
    }
}

// ---------------- launch ----------------
extern "C" void kernel_launch(void* const* d_in, const int* in_sizes, int n_in,
                              void* d_out, int out_size) {
    const float* u  = (const float*)d_in[0];
    const float* x0 = (const float*)d_in[1];
    const float* Wz = (const float*)d_in[2];
    const float* Uz = (const float*)d_in[3];
    const float* bz = (const float*)d_in[4];
    const float* Wf = (const float*)d_in[5];
    const float* Uf = (const float*)d_in[6];
    const float* bf = (const float*)d_in[7];
    const float* Wr = (const float*)d_in[8];
    const float* Ur = (const float*)d_in[9];
    const float* br = (const float*)d_in[10];
    float* out = (float*)d_out;

    init_kernel<<<64, 256>>>(x0);

    dim3 g1(NX_ / BN, (B_ * T_) / BM, 3);
    inproj_kernel<<<g1, 256>>>(u, Wz, Wf, Wr, bz, bf, br);

    // smem: Uzf 16384 + Ur 8192 + bufs 6*4352 + scratch 1024 floats = 206,848 B
    const int smem_bytes = (NX_ * 16 + NX_ * 8 + NBUF * BUFF + 1024) * (int)sizeof(float);
    cudaFuncSetAttribute(recur_kernel, cudaFuncAttributeMaxDynamicSharedMemorySize, smem_bytes);
    recur_kernel<<<GBLKS, RTHREADS, smem_bytes>>>(Uz, Uf, Ur, out);
}